// round 14
// baseline (speedup 1.0000x reference)
#include <cuda_runtime.h>
#include <cuda_bf16.h>
#include <math.h>

#define TT 2048
#define BB 512
#define HH 128
#define ROWS 8
#define NPAIR (BB / ROWS)   // 64 producer/consumer pairs
#define PADH 136            // h row stride (bf16)
#define XPI 264             // xg_if row stride (bf16)
#define PADW 136            // Wih1-half smem row stride (bf16)
#define CHUNK 64            // publish granularity (steps)

typedef unsigned int u32;

// scratch (static device globals: allowed; no cudaMalloc anywhere)
static __device__ __nv_bfloat16 g_xgif[(size_t)BB * TT * 256];  // gates i,f of layer-1 input (+bias)
static __device__ __nv_bfloat16 g_h0[(size_t)BB * TT * HH];     // layer-0 hidden states
static __device__ float g_h1f[BB * HH];                         // final hidden of layer 1
static __device__ u32 g_flag[NPAIR];                            // producer progress flags

__device__ __forceinline__ float tanha(float x) {
    asm("tanh.approx.f32 %0, %0;" : "+f"(x));
    return x;
}
__device__ __forceinline__ float sigm(float x) { return fmaf(tanha(0.5f * x), 0.5f, 0.5f); }

__device__ __forceinline__ u32 pbf2(float a, float b) {
    __nv_bfloat162 t = __floats2bfloat162_rn(a, b);
    return *(u32 *)&t;
}

__device__ __forceinline__ void mma16816(float *c, const u32 *a, const u32 *b) {
    asm volatile(
        "mma.sync.aligned.m16n8k16.row.col.f32.bf16.bf16.f32 "
        "{%0,%1,%2,%3}, {%4,%5,%6,%7}, {%8,%9}, {%0,%1,%2,%3};"
        : "+f"(c[0]), "+f"(c[1]), "+f"(c[2]), "+f"(c[3])
        : "r"(a[0]), "r"(a[1]), "r"(a[2]), "r"(a[3]), "r"(b[0]), "r"(b[1]));
}

__device__ __forceinline__ void ldmx4(u32 &r0, u32 &r1, u32 &r2, u32 &r3, u32 addr) {
    asm volatile("ldmatrix.sync.aligned.m8n8.x4.shared.b16 {%0,%1,%2,%3}, [%4];"
                 : "=r"(r0), "=r"(r1), "=r"(r2), "=r"(r3) : "r"(addr));
}

__device__ __forceinline__ u32 smem_u32(const void *p) {
    u32 a;
    asm("{ .reg .u64 t; cvta.to.shared.u64 t, %1; cvt.u32.u64 %0, t; }" : "=r"(a) : "l"(p));
    return a;
}

__device__ __forceinline__ u32 ld_acq(const u32 *p) {
    u32 v;
    asm volatile("ld.global.acquire.gpu.u32 %0, [%1];" : "=r"(v) : "l"(p) : "memory");
    return v;
}
__device__ __forceinline__ void st_rel(u32 *p, u32 v) {
    asm volatile("st.global.release.gpu.u32 [%0], %1;" :: "l"(p), "r"(v) : "memory");
}

// ============ producer: layer-0 LSTM (fold in fp32) + gemm (gates i,f). 256 threads ============
// Step order: rec MMAs -> gemm MMAs (same b-frags, results deferred) -> pointwise (MUFU hides
// under gemm HMMA drain) -> stores.
__device__ __forceinline__ void producer(
    const float *__restrict__ x, const float *__restrict__ Wih0,
    const float *__restrict__ Whh0, const float *__restrict__ bih0,
    const float *__restrict__ bhh0, const float *__restrict__ Wih1,
    const float *__restrict__ bih1, const float *__restrict__ bhh1, char *smem) {
    __nv_bfloat16 *W1s = (__nv_bfloat16 *)smem;                    // [256][PADW] 69632 B (Wih1 rows 0..255)
    __nv_bfloat16 *hbuf = (__nv_bfloat16 *)(smem + 69632);         // [2][8][PADH] 4352 B
    __nv_bfloat16 *stage = (__nv_bfloat16 *)(smem + 73984);        // [2][8][XPI] 8448 B
    float2 *fslot = (float2 *)(smem + 82432);                      // [2][8] 128 B
    const int tid = threadIdx.x;
    const int w = tid >> 5, lane = tid & 31, gid = lane >> 2, tig = lane & 3;
    const int rb = blockIdx.x * ROWS;
    const int u0 = w * 16 + gid, u1 = u0 + 8;
    const int r0 = 2 * tig, r1 = r0 + 1;

    // Whh0 A-fragments (validated layout)
    u32 a[4][8][4];
#pragma unroll
    for (int g = 0; g < 4; ++g) {
        const int gr0 = g * 128 + u0, gr1 = g * 128 + u1;
#pragma unroll
        for (int kt = 0; kt < 8; ++kt) {
            const int k = kt * 16 + 2 * tig;
            a[g][kt][0] = pbf2(Whh0[(size_t)gr0 * HH + k], Whh0[(size_t)gr0 * HH + k + 1]);
            a[g][kt][1] = pbf2(Whh0[(size_t)gr1 * HH + k], Whh0[(size_t)gr1 * HH + k + 1]);
            a[g][kt][2] = pbf2(Whh0[(size_t)gr0 * HH + k + 8], Whh0[(size_t)gr0 * HH + k + 9]);
            a[g][kt][3] = pbf2(Whh0[(size_t)gr1 * HH + k + 8], Whh0[(size_t)gr1 * HH + k + 9]);
        }
    }
    // layer-0 input weights + fused biases, fp32 (fold on FMA pipe)
    float wiA0[4], wiA1[4], wiB0[4], wiB1[4], bA[4], bB[4];
#pragma unroll
    for (int g = 0; g < 4; ++g) {
        const int ra = g * 128 + u0, rbx = g * 128 + u1;
        wiA0[g] = Wih0[ra * 2]; wiA1[g] = Wih0[ra * 2 + 1]; bA[g] = bih0[ra] + bhh0[ra];
        wiB0[g] = Wih0[rbx * 2]; wiB1[g] = Wih0[rbx * 2 + 1]; bB[g] = bih0[rbx] + bhh0[rbx];
    }
    float bxa[2], bxb[2];
#pragma unroll
    for (int q = 0; q < 2; ++q) {
        bxa[q] = bih1[q * 128 + u0] + bhh1[q * 128 + u0];
        bxb[q] = bih1[q * 128 + u1] + bhh1[q * 128 + u1];
    }
    for (int i = tid; i < 256 * 32; i += 256) {
        int row = i >> 5, kc = i & 31;
        float4 v = *(const float4 *)(Wih1 + (size_t)row * HH + kc * 4);
        *(__nv_bfloat162 *)&W1s[row * PADW + kc * 4] = __floats2bfloat162_rn(v.x, v.y);
        *(__nv_bfloat162 *)&W1s[row * PADW + kc * 4 + 2] = __floats2bfloat162_rn(v.z, v.w);
    }
    const u32 w1b = smem_u32(W1s);
    u32 ldm[2];
#pragma unroll
    for (int q = 0; q < 2; ++q) {
        const int row_l = q * 128 + w * 16 + (lane & 15);
        ldm[q] = w1b + (u32)((row_l * PADW + ((lane & 16) ? 8 : 0)) * 2);
    }
    for (int i = tid; i < 2 * ROWS * PADH / 2; i += 256) ((u32 *)hbuf)[i] = 0u;
    if (tid < ROWS) {
        const float *xp = x + ((size_t)(rb + tid) * TT) * 6;
        fslot[tid] = make_float2(sqrtf(xp[0] * xp[0] + xp[1] * xp[1] + xp[2] * xp[2]),
                                 sqrtf(xp[3] * xp[3] + xp[4] * xp[4] + xp[5] * xp[5]));
    }
    float cst[4] = {0.f, 0.f, 0.f, 0.f};
    u32 *myflag = &g_flag[blockIdx.x];
    __syncthreads();

#pragma unroll 1
    for (int t = 0; t <= TT; ++t) {
        const __nv_bfloat16 *hb = hbuf + (t & 1) * ROWS * PADH;          // h(t-1)
        __nv_bfloat16 *hn = hbuf + ((t + 1) & 1) * ROWS * PADH;          // h(t)
        u32 b[8][2];
#pragma unroll
        for (int kt = 0; kt < 8; ++kt) {
            const int base = gid * PADH + kt * 16 + 2 * tig;
            b[kt][0] = *(const u32 *)&hb[base];
            b[kt][1] = *(const u32 *)&hb[base + 8];
        }
        float pfx = 0.f, pfy = 0.f;
        const bool pfv = (tid < ROWS) && (t + 1 < TT);
        if (pfv) {
            const float *xp = x + ((size_t)(rb + tid) * TT + (t + 1)) * 6;
            pfx = sqrtf(xp[0] * xp[0] + xp[1] * xp[1] + xp[2] * xp[2]);
            pfy = sqrtf(xp[3] * xp[3] + xp[4] * xp[4] + xp[5] * xp[5]);
        }
        // ---- phase 1: rec MMAs (32) ----
        float acc[4][4];
        if (t < TT) {
#pragma unroll
            for (int g = 0; g < 4; ++g) { acc[g][0] = acc[g][1] = acc[g][2] = acc[g][3] = 0.f; }
#pragma unroll
            for (int kt = 0; kt < 8; ++kt)
#pragma unroll
                for (int g = 0; g < 4; ++g) mma16816(acc[g], a[g][kt], b[kt]);
        }
        // ---- phase 2: gemm MMAs issued NOW; xa consumed only in store phase ----
        float xa[2][4];
        if (t > 0) {
            xa[0][0] = xa[0][1] = xa[0][2] = xa[0][3] = 0.f;
            xa[1][0] = xa[1][1] = xa[1][2] = xa[1][3] = 0.f;
#pragma unroll
            for (int kt = 0; kt < 8; ++kt) {
                u32 aw[4];
                ldmx4(aw[0], aw[1], aw[2], aw[3], ldm[0] + kt * 32);
                mma16816(xa[0], aw, b[kt]);
                ldmx4(aw[0], aw[1], aw[2], aw[3], ldm[1] + kt * 32);
                mma16816(xa[1], aw, b[kt]);
            }
        }
        // ---- phase 3: fold + pointwise (MUFU overlaps gemm HMMA drain) ----
        if (t < TT) {
            const float2 fa = fslot[(t & 1) * 8 + r0];
            const float2 fb = fslot[(t & 1) * 8 + r1];
#pragma unroll
            for (int g = 0; g < 4; ++g) {
                acc[g][0] += fmaf(wiA0[g], fa.x, fmaf(wiA1[g], fa.y, bA[g]));
                acc[g][1] += fmaf(wiA0[g], fb.x, fmaf(wiA1[g], fb.y, bA[g]));
                acc[g][2] += fmaf(wiB0[g], fa.x, fmaf(wiB1[g], fa.y, bB[g]));
                acc[g][3] += fmaf(wiB0[g], fb.x, fmaf(wiB1[g], fb.y, bB[g]));
            }
            float h[4];
#pragma unroll
            for (int s = 0; s < 4; ++s) {
                cst[s] = sigm(acc[1][s]) * cst[s] + sigm(acc[0][s]) * tanha(acc[2][s]);
                h[s] = sigm(acc[3][s]) * tanha(cst[s]);
            }
            hn[r0 * PADH + u0] = __float2bfloat16(h[0]);
            hn[r1 * PADH + u0] = __float2bfloat16(h[1]);
            hn[r0 * PADH + u1] = __float2bfloat16(h[2]);
            hn[r1 * PADH + u1] = __float2bfloat16(h[3]);
            if (pfv) fslot[((t + 1) & 1) * 8 + tid] = make_float2(pfx, pfy);
        }
        // ---- phase 4: xg stage stores (reads xa) ----
        if (t > 0) {
            __nv_bfloat16 *stg = stage + (t & 1) * ROWS * XPI;
#pragma unroll
            for (int q = 0; q < 2; ++q) {
                stg[r0 * XPI + q * 128 + u0] = __float2bfloat16(xa[q][0] + bxa[q]);
                stg[r1 * XPI + q * 128 + u0] = __float2bfloat16(xa[q][1] + bxa[q]);
                stg[r0 * XPI + q * 128 + u1] = __float2bfloat16(xa[q][2] + bxb[q]);
                stg[r1 * XPI + q * 128 + u1] = __float2bfloat16(xa[q][3] + bxb[q]);
            }
        }
        __syncthreads();
        // epilogue: coalesced global stores
        if (t < TT && tid < 128) {
            const int row = tid >> 4, q = tid & 15;
            uint4 v = *(const uint4 *)&hn[row * PADH + q * 8];
            *(uint4 *)(g_h0 + ((size_t)(rb + row) * TT + t) * HH + q * 8) = v;
        }
        if (t > 0) {
            const __nv_bfloat16 *stg = stage + (t & 1) * ROWS * XPI;
            const int row = tid >> 5, seg = tid & 31;
            uint4 v = *(const uint4 *)&stg[row * XPI + seg * 8];
            *(uint4 *)(g_xgif + ((size_t)(rb + row) * TT + (t - 1)) * 256 + seg * 8) = v;
            if ((t & (CHUNK - 1)) == 0) {
                __threadfence();
                __syncthreads();
                if (tid == 0) st_rel(myflag, (u32)t);
            }
        }
    }
}

// ===== consumer: layer-1 LSTM + gemm (gates g,o) from h0. 256 threads (unchanged R12) =====
__device__ __forceinline__ void consumer(
    const float *__restrict__ Whh1, const float *__restrict__ Wih1,
    const float *__restrict__ bih1, const float *__restrict__ bhh1, char *smem) {
    __nv_bfloat16 *hbuf = (__nv_bfloat16 *)smem;                   // [2][8][PADH] 4352 B
    __nv_bfloat16 *h0buf = (__nv_bfloat16 *)(smem + 4352);         // [2][8][PADH] 4352 B
    __nv_bfloat16 *xifbuf = (__nv_bfloat16 *)(smem + 8704);        // [2][8][XPI] 8448 B
    __nv_bfloat16 *W1s = (__nv_bfloat16 *)(smem + 17152);          // [256][PADW] 69632 B (rows 256..511)
    const int tid = threadIdx.x;
    const int w = tid >> 5, lane = tid & 31, gid = lane >> 2, tig = lane & 3;
    const int p = blockIdx.x - NPAIR;
    const int rb = p * ROWS;
    const int u0 = w * 16 + gid, u1 = u0 + 8;
    const int r0 = 2 * tig, r1 = r0 + 1;
    const u32 *myflag = &g_flag[p];

    u32 a[4][8][4];
#pragma unroll
    for (int g = 0; g < 4; ++g) {
        const int gr0 = g * 128 + u0, gr1 = g * 128 + u1;
#pragma unroll
        for (int kt = 0; kt < 8; ++kt) {
            const int k = kt * 16 + 2 * tig;
            a[g][kt][0] = pbf2(Whh1[(size_t)gr0 * HH + k], Whh1[(size_t)gr0 * HH + k + 1]);
            a[g][kt][1] = pbf2(Whh1[(size_t)gr1 * HH + k], Whh1[(size_t)gr1 * HH + k + 1]);
            a[g][kt][2] = pbf2(Whh1[(size_t)gr0 * HH + k + 8], Whh1[(size_t)gr0 * HH + k + 9]);
            a[g][kt][3] = pbf2(Whh1[(size_t)gr1 * HH + k + 8], Whh1[(size_t)gr1 * HH + k + 9]);
        }
    }
    const float bg0 = bih1[256 + u0] + bhh1[256 + u0];
    const float bg1 = bih1[256 + u1] + bhh1[256 + u1];
    const float bo0 = bih1[384 + u0] + bhh1[384 + u0];
    const float bo1 = bih1[384 + u1] + bhh1[384 + u1];
    for (int i = tid; i < 256 * 32; i += 256) {
        int row = i >> 5, kc = i & 31;
        float4 v = *(const float4 *)(Wih1 + (size_t)(256 + row) * HH + kc * 4);
        *(__nv_bfloat162 *)&W1s[row * PADW + kc * 4] = __floats2bfloat162_rn(v.x, v.y);
        *(__nv_bfloat162 *)&W1s[row * PADW + kc * 4 + 2] = __floats2bfloat162_rn(v.z, v.w);
    }
    const u32 w1b = smem_u32(W1s);
    u32 ldm[2];
#pragma unroll
    for (int q = 0; q < 2; ++q) {
        const int row_l = q * 128 + w * 16 + (lane & 15);
        ldm[q] = w1b + (u32)((row_l * PADW + ((lane & 16) ? 8 : 0)) * 2);
    }
    for (int i = tid; i < 2 * ROWS * PADH / 2; i += 256) ((u32 *)hbuf)[i] = 0u;
    const int xrow = tid >> 5, xseg = tid & 31;
    const int hrow = tid >> 4, hseg = tid & 15;
    u32 seen = ld_acq(myflag);
    while (seen < 1u) { __nanosleep(256); seen = ld_acq(myflag); }
    {
        uint4 v = *(const uint4 *)(g_xgif + ((size_t)(rb + xrow) * TT) * 256 + xseg * 8);
        *(uint4 *)&xifbuf[xrow * XPI + xseg * 8] = v;
        if (tid < 128) {
            uint4 hv = *(const uint4 *)(g_h0 + ((size_t)(rb + hrow) * TT) * HH + hseg * 8);
            *(uint4 *)&h0buf[hrow * PADH + hseg * 8] = hv;
        }
    }
    float cst[4] = {0.f, 0.f, 0.f, 0.f};
    __syncthreads();

#pragma unroll 1
    for (int t = 0; t < TT; ++t) {
        const int hasn = (t + 1 < TT);
        uint4 pfx, pfh;
        if (hasn) {
            const u32 need = (u32)(t + 2);
            if (seen < need) {
                seen = ld_acq(myflag);
                while (seen < need) { __nanosleep(128); seen = ld_acq(myflag); }
            }
            pfx = *(const uint4 *)(g_xgif + ((size_t)(rb + xrow) * TT + (t + 1)) * 256 + xseg * 8);
            if (tid < 128)
                pfh = *(const uint4 *)(g_h0 + ((size_t)(rb + hrow) * TT + (t + 1)) * HH + hseg * 8);
        }
        const __nv_bfloat16 *xb = xifbuf + (t & 1) * ROWS * XPI;
        const __nv_bfloat16 *hb = hbuf + (t & 1) * ROWS * PADH;
        const __nv_bfloat16 *h0b = h0buf + (t & 1) * ROWS * PADH;
        __nv_bfloat16 *hn = hbuf + ((t + 1) & 1) * ROWS * PADH;
        u32 b[8][2], b0[8][2];
#pragma unroll
        for (int kt = 0; kt < 8; ++kt) {
            const int base = gid * PADH + kt * 16 + 2 * tig;
            b[kt][0] = *(const u32 *)&hb[base];
            b[kt][1] = *(const u32 *)&hb[base + 8];
            b0[kt][0] = *(const u32 *)&h0b[base];
            b0[kt][1] = *(const u32 *)&h0b[base + 8];
        }
        float acc[4][4];
#pragma unroll
        for (int g = 0; g < 4; ++g) { acc[g][0] = acc[g][1] = acc[g][2] = acc[g][3] = 0.f; }
#pragma unroll
        for (int kt = 0; kt < 8; ++kt)
#pragma unroll
            for (int g = 0; g < 4; ++g) mma16816(acc[g], a[g][kt], b[kt]);
        float xa[2][4];
        xa[0][0] = xa[0][1] = xa[0][2] = xa[0][3] = 0.f;
        xa[1][0] = xa[1][1] = xa[1][2] = xa[1][3] = 0.f;
#pragma unroll
        for (int kt = 0; kt < 8; ++kt) {
            u32 aw[4];
            ldmx4(aw[0], aw[1], aw[2], aw[3], ldm[0] + kt * 32);
            mma16816(xa[0], aw, b0[kt]);
            ldmx4(aw[0], aw[1], aw[2], aw[3], ldm[1] + kt * 32);
            mma16816(xa[1], aw, b0[kt]);
        }
        const float gi0 = acc[0][0] + __bfloat162float(xb[r0 * XPI + u0]);
        const float gi1 = acc[0][1] + __bfloat162float(xb[r1 * XPI + u0]);
        const float gi2 = acc[0][2] + __bfloat162float(xb[r0 * XPI + u1]);
        const float gi3 = acc[0][3] + __bfloat162float(xb[r1 * XPI + u1]);
        const float gf0 = acc[1][0] + __bfloat162float(xb[r0 * XPI + 128 + u0]);
        const float gf1 = acc[1][1] + __bfloat162float(xb[r1 * XPI + 128 + u0]);
        const float gf2 = acc[1][2] + __bfloat162float(xb[r0 * XPI + 128 + u1]);
        const float gf3 = acc[1][3] + __bfloat162float(xb[r1 * XPI + 128 + u1]);
        const float gg0 = acc[2][0] + xa[0][0] + bg0;
        const float gg1 = acc[2][1] + xa[0][1] + bg0;
        const float gg2 = acc[2][2] + xa[0][2] + bg1;
        const float gg3 = acc[2][3] + xa[0][3] + bg1;
        const float go0 = acc[3][0] + xa[1][0] + bo0;
        const float go1 = acc[3][1] + xa[1][1] + bo0;
        const float go2 = acc[3][2] + xa[1][2] + bo1;
        const float go3 = acc[3][3] + xa[1][3] + bo1;
        float h[4];
        cst[0] = sigm(gf0) * cst[0] + sigm(gi0) * tanha(gg0);
        h[0] = sigm(go0) * tanha(cst[0]);
        cst[1] = sigm(gf1) * cst[1] + sigm(gi1) * tanha(gg1);
        h[1] = sigm(go1) * tanha(cst[1]);
        cst[2] = sigm(gf2) * cst[2] + sigm(gi2) * tanha(gg2);
        h[2] = sigm(go2) * tanha(cst[2]);
        cst[3] = sigm(gf3) * cst[3] + sigm(gi3) * tanha(gg3);
        h[3] = sigm(go3) * tanha(cst[3]);
        hn[r0 * PADH + u0] = __float2bfloat16(h[0]);
        hn[r1 * PADH + u0] = __float2bfloat16(h[1]);
        hn[r0 * PADH + u1] = __float2bfloat16(h[2]);
        hn[r1 * PADH + u1] = __float2bfloat16(h[3]);
        if (hasn) {
            __nv_bfloat16 *xn = xifbuf + ((t + 1) & 1) * ROWS * XPI;
            *(uint4 *)&xn[xrow * XPI + xseg * 8] = pfx;
            if (tid < 128) {
                __nv_bfloat16 *h0n = h0buf + ((t + 1) & 1) * ROWS * PADH;
                *(uint4 *)&h0n[hrow * PADH + hseg * 8] = pfh;
            }
        } else {
            g_h1f[(rb + r0) * HH + u0] = h[0];
            g_h1f[(rb + r1) * HH + u0] = h[1];
            g_h1f[(rb + r0) * HH + u1] = h[2];
            g_h1f[(rb + r1) * HH + u1] = h[3];
        }
        __syncthreads();
    }
}

extern "C" __global__ void __launch_bounds__(256, 1)
k_pipe(const float *__restrict__ x, const float *__restrict__ Wih0,
       const float *__restrict__ Whh0, const float *__restrict__ bih0,
       const float *__restrict__ bhh0, const float *__restrict__ Wih1,
       const float *__restrict__ Whh1, const float *__restrict__ bih1,
       const float *__restrict__ bhh1) {
    extern __shared__ char smem[];
    if (blockIdx.x < NPAIR)
        producer(x, Wih0, Whh0, bih0, bhh0, Wih1, bih1, bhh1, smem);
    else
        consumer(Whh1, Wih1, bih1, bhh1, smem);
}

extern "C" __global__ void k_reset() {
    if (threadIdx.x < NPAIR) g_flag[threadIdx.x] = 0u;
}

// ================= classifier MLP + double softmax =================
extern "C" __global__ void __launch_bounds__(128)
k_cls(const float *__restrict__ W1, const float *__restrict__ b1,
      const float *__restrict__ W2, const float *__restrict__ b2,
      const float *__restrict__ W3, const float *__restrict__ b3,
      float *__restrict__ out) {
    __shared__ float hb[128], z1[128], z2[64], z3[8];
    const int tid = threadIdx.x;
    const int row = blockIdx.x;
    hb[tid] = g_h1f[row * HH + tid];
    __syncthreads();
    float a = b1[tid];
#pragma unroll 4
    for (int k = 0; k < 128; ++k) a = fmaf(W1[tid * 128 + k], hb[k], a);
    z1[tid] = fmaxf(a, 0.f);
    __syncthreads();
    if (tid < 64) {
        float s = b2[tid];
#pragma unroll 4
        for (int k = 0; k < 128; ++k) s = fmaf(W2[tid * 128 + k], z1[k], s);
        z2[tid] = fmaxf(s, 0.f);
    }
    __syncthreads();
    if (tid < 6) {
        float s = b3[tid];
#pragma unroll 4
        for (int k = 0; k < 64; ++k) s = fmaf(W3[tid * 64 + k], z2[k], s);
        z3[tid] = s;
    }
    __syncthreads();
    if (tid == 0) {
        float v[6];
#pragma unroll
        for (int i = 0; i < 6; ++i) v[i] = z3[i];
#pragma unroll
        for (int p = 0; p < 2; ++p) {
            float m = v[0];
            for (int i = 1; i < 6; ++i) m = fmaxf(m, v[i]);
            float s = 0.f;
            for (int i = 0; i < 6; ++i) { v[i] = expf(v[i] - m); s += v[i]; }
            float inv = 1.f / s;
            for (int i = 0; i < 6; ++i) v[i] *= inv;
        }
        for (int i = 0; i < 6; ++i) out[row * 6 + i] = v[i];
    }
}

extern "C" void kernel_launch(void *const *d_in, const int *in_sizes, int n_in,
                              void *d_out, int out_size) {
    const float *x = (const float *)d_in[0];
    const float *Wih0 = (const float *)d_in[1];
    const float *Whh0 = (const float *)d_in[2];
    const float *bih0 = (const float *)d_in[3];
    const float *bhh0 = (const float *)d_in[4];
    const float *Wih1 = (const float *)d_in[5];
    const float *Whh1 = (const float *)d_in[6];
    const float *bih1 = (const float *)d_in[7];
    const float *bhh1 = (const float *)d_in[8];
    const float *W1 = (const float *)d_in[9];
    const float *b1 = (const float *)d_in[10];
    const float *W2 = (const float *)d_in[11];
    const float *b2 = (const float *)d_in[12];
    const float *W3 = (const float *)d_in[13];
    const float *b3 = (const float *)d_in[14];
    float *out = (float *)d_out;

    const int SMEMP = 17152 + 69632;  // 86784
    cudaFuncSetAttribute(k_pipe, cudaFuncAttributeMaxDynamicSharedMemorySize, SMEMP);

    k_reset<<<1, 64>>>();
    k_pipe<<<2 * NPAIR, 256, SMEMP>>>(x, Wih0, Whh0, bih0, bhh0, Wih1, Whh1, bih1, bhh1);
    k_cls<<<BB, 128>>>(W1, b1, W2, b2, W3, b3, out);
}

// round 15
// speedup vs baseline: 1.0904x; 1.0904x over previous
#include <cuda_runtime.h>
#include <cuda_bf16.h>
#include <math.h>

#define TT 2048
#define BB 512
#define HH 128
#define ROWS 8
#define NPAIR (BB / ROWS)   // 64 producer/consumer pairs
#define PADH 136            // h row stride (bf16)
#define XPI 264             // xg_if row stride (bf16)
#define PADW 136            // Wih1-half smem row stride (bf16)
#define CHUNK 64            // publish granularity (steps)

typedef unsigned int u32;

// scratch (static device globals: allowed; no cudaMalloc anywhere)
static __device__ __nv_bfloat16 g_xgif[(size_t)BB * TT * 256];  // gates i,f of layer-1 input (+bias)
static __device__ __nv_bfloat16 g_h0[(size_t)BB * TT * HH];     // layer-0 hidden states
static __device__ float g_h1f[BB * HH];                         // final hidden of layer 1
static __device__ u32 g_flag[NPAIR];                            // producer progress flags

__device__ __forceinline__ float tanha(float x) {
    asm("tanh.approx.f32 %0, %0;" : "+f"(x));
    return x;
}
__device__ __forceinline__ float sigm(float x) { return fmaf(tanha(0.5f * x), 0.5f, 0.5f); }

__device__ __forceinline__ u32 pbf2(float a, float b) {
    __nv_bfloat162 t = __floats2bfloat162_rn(a, b);
    return *(u32 *)&t;
}

__device__ __forceinline__ void mma16816(float *c, const u32 *a, const u32 *b) {
    asm volatile(
        "mma.sync.aligned.m16n8k16.row.col.f32.bf16.bf16.f32 "
        "{%0,%1,%2,%3}, {%4,%5,%6,%7}, {%8,%9}, {%0,%1,%2,%3};"
        : "+f"(c[0]), "+f"(c[1]), "+f"(c[2]), "+f"(c[3])
        : "r"(a[0]), "r"(a[1]), "r"(a[2]), "r"(a[3]), "r"(b[0]), "r"(b[1]));
}

__device__ __forceinline__ void ldmx4(u32 &r0, u32 &r1, u32 &r2, u32 &r3, u32 addr) {
    asm volatile("ldmatrix.sync.aligned.m8n8.x4.shared.b16 {%0,%1,%2,%3}, [%4];"
                 : "=r"(r0), "=r"(r1), "=r"(r2), "=r"(r3) : "r"(addr));
}

__device__ __forceinline__ u32 smem_u32(const void *p) {
    u32 a;
    asm("{ .reg .u64 t; cvta.to.shared.u64 t, %1; cvt.u32.u64 %0, t; }" : "=r"(a) : "l"(p));
    return a;
}

__device__ __forceinline__ u32 ld_acq(const u32 *p) {
    u32 v;
    asm volatile("ld.global.acquire.gpu.u32 %0, [%1];" : "=r"(v) : "l"(p) : "memory");
    return v;
}
__device__ __forceinline__ void st_rel(u32 *p, u32 v) {
    asm volatile("st.global.release.gpu.u32 [%0], %1;" :: "l"(p), "r"(v) : "memory");
}

// ============ producer: layer-0 LSTM (fold in fp32) + gemm (gates i,f). 256 threads ============
// EXACT R12 structure (best known): rec MMAs -> fold+pointwise -> gemm MMAs -> stores.
__device__ __forceinline__ void producer(
    const float *__restrict__ x, const float *__restrict__ Wih0,
    const float *__restrict__ Whh0, const float *__restrict__ bih0,
    const float *__restrict__ bhh0, const float *__restrict__ Wih1,
    const float *__restrict__ bih1, const float *__restrict__ bhh1, char *smem) {
    __nv_bfloat16 *W1s = (__nv_bfloat16 *)smem;                    // [256][PADW] 69632 B (Wih1 rows 0..255)
    __nv_bfloat16 *hbuf = (__nv_bfloat16 *)(smem + 69632);         // [2][8][PADH] 4352 B
    __nv_bfloat16 *stage = (__nv_bfloat16 *)(smem + 73984);        // [2][8][XPI] 8448 B
    float2 *fslot = (float2 *)(smem + 82432);                      // [2][8] 128 B
    const int tid = threadIdx.x;
    const int w = tid >> 5, lane = tid & 31, gid = lane >> 2, tig = lane & 3;
    const int rb = blockIdx.x * ROWS;
    const int u0 = w * 16 + gid, u1 = u0 + 8;
    const int r0 = 2 * tig, r1 = r0 + 1;

    u32 a[4][8][4];
#pragma unroll
    for (int g = 0; g < 4; ++g) {
        const int gr0 = g * 128 + u0, gr1 = g * 128 + u1;
#pragma unroll
        for (int kt = 0; kt < 8; ++kt) {
            const int k = kt * 16 + 2 * tig;
            a[g][kt][0] = pbf2(Whh0[(size_t)gr0 * HH + k], Whh0[(size_t)gr0 * HH + k + 1]);
            a[g][kt][1] = pbf2(Whh0[(size_t)gr1 * HH + k], Whh0[(size_t)gr1 * HH + k + 1]);
            a[g][kt][2] = pbf2(Whh0[(size_t)gr0 * HH + k + 8], Whh0[(size_t)gr0 * HH + k + 9]);
            a[g][kt][3] = pbf2(Whh0[(size_t)gr1 * HH + k + 8], Whh0[(size_t)gr1 * HH + k + 9]);
        }
    }
    float wiA0[4], wiA1[4], wiB0[4], wiB1[4], bA[4], bB[4];
#pragma unroll
    for (int g = 0; g < 4; ++g) {
        const int ra = g * 128 + u0, rbx = g * 128 + u1;
        wiA0[g] = Wih0[ra * 2]; wiA1[g] = Wih0[ra * 2 + 1]; bA[g] = bih0[ra] + bhh0[ra];
        wiB0[g] = Wih0[rbx * 2]; wiB1[g] = Wih0[rbx * 2 + 1]; bB[g] = bih0[rbx] + bhh0[rbx];
    }
    float bxa[2], bxb[2];
#pragma unroll
    for (int q = 0; q < 2; ++q) {
        bxa[q] = bih1[q * 128 + u0] + bhh1[q * 128 + u0];
        bxb[q] = bih1[q * 128 + u1] + bhh1[q * 128 + u1];
    }
    for (int i = tid; i < 256 * 32; i += 256) {
        int row = i >> 5, kc = i & 31;
        float4 v = *(const float4 *)(Wih1 + (size_t)row * HH + kc * 4);
        *(__nv_bfloat162 *)&W1s[row * PADW + kc * 4] = __floats2bfloat162_rn(v.x, v.y);
        *(__nv_bfloat162 *)&W1s[row * PADW + kc * 4 + 2] = __floats2bfloat162_rn(v.z, v.w);
    }
    const u32 w1b = smem_u32(W1s);
    u32 ldm[2];
#pragma unroll
    for (int q = 0; q < 2; ++q) {
        const int row_l = q * 128 + w * 16 + (lane & 15);
        ldm[q] = w1b + (u32)((row_l * PADW + ((lane & 16) ? 8 : 0)) * 2);
    }
    for (int i = tid; i < 2 * ROWS * PADH / 2; i += 256) ((u32 *)hbuf)[i] = 0u;
    if (tid < ROWS) {
        const float *xp = x + ((size_t)(rb + tid) * TT) * 6;
        fslot[tid] = make_float2(sqrtf(xp[0] * xp[0] + xp[1] * xp[1] + xp[2] * xp[2]),
                                 sqrtf(xp[3] * xp[3] + xp[4] * xp[4] + xp[5] * xp[5]));
    }
    float cst[4] = {0.f, 0.f, 0.f, 0.f};
    u32 *myflag = &g_flag[blockIdx.x];
    __syncthreads();

#pragma unroll 1
    for (int t = 0; t <= TT; ++t) {
        const __nv_bfloat16 *hb = hbuf + (t & 1) * ROWS * PADH;          // h(t-1)
        __nv_bfloat16 *hn = hbuf + ((t + 1) & 1) * ROWS * PADH;          // h(t)
        u32 b[8][2];
#pragma unroll
        for (int kt = 0; kt < 8; ++kt) {
            const int base = gid * PADH + kt * 16 + 2 * tig;
            b[kt][0] = *(const u32 *)&hb[base];
            b[kt][1] = *(const u32 *)&hb[base + 8];
        }
        float pfx = 0.f, pfy = 0.f;
        const bool pfv = (tid < ROWS) && (t + 1 < TT);
        if (pfv) {
            const float *xp = x + ((size_t)(rb + tid) * TT + (t + 1)) * 6;
            pfx = sqrtf(xp[0] * xp[0] + xp[1] * xp[1] + xp[2] * xp[2]);
            pfy = sqrtf(xp[3] * xp[3] + xp[4] * xp[4] + xp[5] * xp[5]);
        }
        if (t < TT) {
            float acc[4][4];
#pragma unroll
            for (int g = 0; g < 4; ++g) { acc[g][0] = acc[g][1] = acc[g][2] = acc[g][3] = 0.f; }
#pragma unroll
            for (int kt = 0; kt < 8; ++kt)
#pragma unroll
                for (int g = 0; g < 4; ++g) mma16816(acc[g], a[g][kt], b[kt]);
            const float2 fa = fslot[(t & 1) * 8 + r0];
            const float2 fb = fslot[(t & 1) * 8 + r1];
#pragma unroll
            for (int g = 0; g < 4; ++g) {
                acc[g][0] += fmaf(wiA0[g], fa.x, fmaf(wiA1[g], fa.y, bA[g]));
                acc[g][1] += fmaf(wiA0[g], fb.x, fmaf(wiA1[g], fb.y, bA[g]));
                acc[g][2] += fmaf(wiB0[g], fa.x, fmaf(wiB1[g], fa.y, bB[g]));
                acc[g][3] += fmaf(wiB0[g], fb.x, fmaf(wiB1[g], fb.y, bB[g]));
            }
            float h[4];
#pragma unroll
            for (int s = 0; s < 4; ++s) {
                cst[s] = sigm(acc[1][s]) * cst[s] + sigm(acc[0][s]) * tanha(acc[2][s]);
                h[s] = sigm(acc[3][s]) * tanha(cst[s]);
            }
            hn[r0 * PADH + u0] = __float2bfloat16(h[0]);
            hn[r1 * PADH + u0] = __float2bfloat16(h[1]);
            hn[r0 * PADH + u1] = __float2bfloat16(h[2]);
            hn[r1 * PADH + u1] = __float2bfloat16(h[3]);
            if (pfv) fslot[((t + 1) & 1) * 8 + tid] = make_float2(pfx, pfy);
        }
        if (t > 0) {
            float xa[2][4];
            xa[0][0] = xa[0][1] = xa[0][2] = xa[0][3] = 0.f;
            xa[1][0] = xa[1][1] = xa[1][2] = xa[1][3] = 0.f;
#pragma unroll
            for (int kt = 0; kt < 8; ++kt) {
                u32 aw[4];
                ldmx4(aw[0], aw[1], aw[2], aw[3], ldm[0] + kt * 32);
                mma16816(xa[0], aw, b[kt]);
                ldmx4(aw[0], aw[1], aw[2], aw[3], ldm[1] + kt * 32);
                mma16816(xa[1], aw, b[kt]);
            }
            __nv_bfloat16 *stg = stage + (t & 1) * ROWS * XPI;
#pragma unroll
            for (int q = 0; q < 2; ++q) {
                stg[r0 * XPI + q * 128 + u0] = __float2bfloat16(xa[q][0] + bxa[q]);
                stg[r1 * XPI + q * 128 + u0] = __float2bfloat16(xa[q][1] + bxa[q]);
                stg[r0 * XPI + q * 128 + u1] = __float2bfloat16(xa[q][2] + bxb[q]);
                stg[r1 * XPI + q * 128 + u1] = __float2bfloat16(xa[q][3] + bxb[q]);
            }
        }
        __syncthreads();
        if (t < TT && tid < 128) {
            const int row = tid >> 4, q = tid & 15;
            uint4 v = *(const uint4 *)&hn[row * PADH + q * 8];
            *(uint4 *)(g_h0 + ((size_t)(rb + row) * TT + t) * HH + q * 8) = v;
        }
        if (t > 0) {
            const __nv_bfloat16 *stg = stage + (t & 1) * ROWS * XPI;
            const int row = tid >> 5, seg = tid & 31;
            uint4 v = *(const uint4 *)&stg[row * XPI + seg * 8];
            *(uint4 *)(g_xgif + ((size_t)(rb + row) * TT + (t - 1)) * 256 + seg * 8) = v;
            if ((t & (CHUNK - 1)) == 0) {
                __threadfence();
                __syncthreads();
                if (tid == 0) st_rel(myflag, (u32)t);
            }
        }
    }
}

// ===== consumer: layer-1 LSTM + gemm (gates g,o) from h0. 256 threads (exact R12) =====
__device__ __forceinline__ void consumer(
    const float *__restrict__ Whh1, const float *__restrict__ Wih1,
    const float *__restrict__ bih1, const float *__restrict__ bhh1, char *smem) {
    __nv_bfloat16 *hbuf = (__nv_bfloat16 *)smem;                   // [2][8][PADH] 4352 B
    __nv_bfloat16 *h0buf = (__nv_bfloat16 *)(smem + 4352);         // [2][8][PADH] 4352 B
    __nv_bfloat16 *xifbuf = (__nv_bfloat16 *)(smem + 8704);        // [2][8][XPI] 8448 B
    __nv_bfloat16 *W1s = (__nv_bfloat16 *)(smem + 17152);          // [256][PADW] 69632 B (rows 256..511)
    const int tid = threadIdx.x;
    const int w = tid >> 5, lane = tid & 31, gid = lane >> 2, tig = lane & 3;
    const int p = blockIdx.x - NPAIR;
    const int rb = p * ROWS;
    const int u0 = w * 16 + gid, u1 = u0 + 8;
    const int r0 = 2 * tig, r1 = r0 + 1;
    const u32 *myflag = &g_flag[p];

    u32 a[4][8][4];
#pragma unroll
    for (int g = 0; g < 4; ++g) {
        const int gr0 = g * 128 + u0, gr1 = g * 128 + u1;
#pragma unroll
        for (int kt = 0; kt < 8; ++kt) {
            const int k = kt * 16 + 2 * tig;
            a[g][kt][0] = pbf2(Whh1[(size_t)gr0 * HH + k], Whh1[(size_t)gr0 * HH + k + 1]);
            a[g][kt][1] = pbf2(Whh1[(size_t)gr1 * HH + k], Whh1[(size_t)gr1 * HH + k + 1]);
            a[g][kt][2] = pbf2(Whh1[(size_t)gr0 * HH + k + 8], Whh1[(size_t)gr0 * HH + k + 9]);
            a[g][kt][3] = pbf2(Whh1[(size_t)gr1 * HH + k + 8], Whh1[(size_t)gr1 * HH + k + 9]);
        }
    }
    const float bg0 = bih1[256 + u0] + bhh1[256 + u0];
    const float bg1 = bih1[256 + u1] + bhh1[256 + u1];
    const float bo0 = bih1[384 + u0] + bhh1[384 + u0];
    const float bo1 = bih1[384 + u1] + bhh1[384 + u1];
    for (int i = tid; i < 256 * 32; i += 256) {
        int row = i >> 5, kc = i & 31;
        float4 v = *(const float4 *)(Wih1 + (size_t)(256 + row) * HH + kc * 4);
        *(__nv_bfloat162 *)&W1s[row * PADW + kc * 4] = __floats2bfloat162_rn(v.x, v.y);
        *(__nv_bfloat162 *)&W1s[row * PADW + kc * 4 + 2] = __floats2bfloat162_rn(v.z, v.w);
    }
    const u32 w1b = smem_u32(W1s);
    u32 ldm[2];
#pragma unroll
    for (int q = 0; q < 2; ++q) {
        const int row_l = q * 128 + w * 16 + (lane & 15);
        ldm[q] = w1b + (u32)((row_l * PADW + ((lane & 16) ? 8 : 0)) * 2);
    }
    for (int i = tid; i < 2 * ROWS * PADH / 2; i += 256) ((u32 *)hbuf)[i] = 0u;
    const int xrow = tid >> 5, xseg = tid & 31;
    const int hrow = tid >> 4, hseg = tid & 15;
    u32 seen = ld_acq(myflag);
    while (seen < 1u) { __nanosleep(256); seen = ld_acq(myflag); }
    {
        uint4 v = *(const uint4 *)(g_xgif + ((size_t)(rb + xrow) * TT) * 256 + xseg * 8);
        *(uint4 *)&xifbuf[xrow * XPI + xseg * 8] = v;
        if (tid < 128) {
            uint4 hv = *(const uint4 *)(g_h0 + ((size_t)(rb + hrow) * TT) * HH + hseg * 8);
            *(uint4 *)&h0buf[hrow * PADH + hseg * 8] = hv;
        }
    }
    float cst[4] = {0.f, 0.f, 0.f, 0.f};
    __syncthreads();

#pragma unroll 1
    for (int t = 0; t < TT; ++t) {
        const int hasn = (t + 1 < TT);
        uint4 pfx, pfh;
        if (hasn) {
            const u32 need = (u32)(t + 2);
            if (seen < need) {
                seen = ld_acq(myflag);
                while (seen < need) { __nanosleep(128); seen = ld_acq(myflag); }
            }
            pfx = *(const uint4 *)(g_xgif + ((size_t)(rb + xrow) * TT + (t + 1)) * 256 + xseg * 8);
            if (tid < 128)
                pfh = *(const uint4 *)(g_h0 + ((size_t)(rb + hrow) * TT + (t + 1)) * HH + hseg * 8);
        }
        const __nv_bfloat16 *xb = xifbuf + (t & 1) * ROWS * XPI;
        const __nv_bfloat16 *hb = hbuf + (t & 1) * ROWS * PADH;
        const __nv_bfloat16 *h0b = h0buf + (t & 1) * ROWS * PADH;
        __nv_bfloat16 *hn = hbuf + ((t + 1) & 1) * ROWS * PADH;
        u32 b[8][2], b0[8][2];
#pragma unroll
        for (int kt = 0; kt < 8; ++kt) {
            const int base = gid * PADH + kt * 16 + 2 * tig;
            b[kt][0] = *(const u32 *)&hb[base];
            b[kt][1] = *(const u32 *)&hb[base + 8];
            b0[kt][0] = *(const u32 *)&h0b[base];
            b0[kt][1] = *(const u32 *)&h0b[base + 8];
        }
        float acc[4][4];
#pragma unroll
        for (int g = 0; g < 4; ++g) { acc[g][0] = acc[g][1] = acc[g][2] = acc[g][3] = 0.f; }
#pragma unroll
        for (int kt = 0; kt < 8; ++kt)
#pragma unroll
            for (int g = 0; g < 4; ++g) mma16816(acc[g], a[g][kt], b[kt]);
        float xa[2][4];
        xa[0][0] = xa[0][1] = xa[0][2] = xa[0][3] = 0.f;
        xa[1][0] = xa[1][1] = xa[1][2] = xa[1][3] = 0.f;
#pragma unroll
        for (int kt = 0; kt < 8; ++kt) {
            u32 aw[4];
            ldmx4(aw[0], aw[1], aw[2], aw[3], ldm[0] + kt * 32);
            mma16816(xa[0], aw, b0[kt]);
            ldmx4(aw[0], aw[1], aw[2], aw[3], ldm[1] + kt * 32);
            mma16816(xa[1], aw, b0[kt]);
        }
        const float gi0 = acc[0][0] + __bfloat162float(xb[r0 * XPI + u0]);
        const float gi1 = acc[0][1] + __bfloat162float(xb[r1 * XPI + u0]);
        const float gi2 = acc[0][2] + __bfloat162float(xb[r0 * XPI + u1]);
        const float gi3 = acc[0][3] + __bfloat162float(xb[r1 * XPI + u1]);
        const float gf0 = acc[1][0] + __bfloat162float(xb[r0 * XPI + 128 + u0]);
        const float gf1 = acc[1][1] + __bfloat162float(xb[r1 * XPI + 128 + u0]);
        const float gf2 = acc[1][2] + __bfloat162float(xb[r0 * XPI + 128 + u1]);
        const float gf3 = acc[1][3] + __bfloat162float(xb[r1 * XPI + 128 + u1]);
        const float gg0 = acc[2][0] + xa[0][0] + bg0;
        const float gg1 = acc[2][1] + xa[0][1] + bg0;
        const float gg2 = acc[2][2] + xa[0][2] + bg1;
        const float gg3 = acc[2][3] + xa[0][3] + bg1;
        const float go0 = acc[3][0] + xa[1][0] + bo0;
        const float go1 = acc[3][1] + xa[1][1] + bo0;
        const float go2 = acc[3][2] + xa[1][2] + bo1;
        const float go3 = acc[3][3] + xa[1][3] + bo1;
        float h[4];
        cst[0] = sigm(gf0) * cst[0] + sigm(gi0) * tanha(gg0);
        h[0] = sigm(go0) * tanha(cst[0]);
        cst[1] = sigm(gf1) * cst[1] + sigm(gi1) * tanha(gg1);
        h[1] = sigm(go1) * tanha(cst[1]);
        cst[2] = sigm(gf2) * cst[2] + sigm(gi2) * tanha(gg2);
        h[2] = sigm(go2) * tanha(cst[2]);
        cst[3] = sigm(gf3) * cst[3] + sigm(gi3) * tanha(gg3);
        h[3] = sigm(go3) * tanha(cst[3]);
        hn[r0 * PADH + u0] = __float2bfloat16(h[0]);
        hn[r1 * PADH + u0] = __float2bfloat16(h[1]);
        hn[r0 * PADH + u1] = __float2bfloat16(h[2]);
        hn[r1 * PADH + u1] = __float2bfloat16(h[3]);
        if (hasn) {
            __nv_bfloat16 *xn = xifbuf + ((t + 1) & 1) * ROWS * XPI;
            *(uint4 *)&xn[xrow * XPI + xseg * 8] = pfx;
            if (tid < 128) {
                __nv_bfloat16 *h0n = h0buf + ((t + 1) & 1) * ROWS * PADH;
                *(uint4 *)&h0n[hrow * PADH + hseg * 8] = pfh;
            }
        } else {
            g_h1f[(rb + r0) * HH + u0] = h[0];
            g_h1f[(rb + r1) * HH + u0] = h[1];
            g_h1f[(rb + r0) * HH + u1] = h[2];
            g_h1f[(rb + r1) * HH + u1] = h[3];
        }
        __syncthreads();
    }
}

extern "C" __global__ void __launch_bounds__(256, 1)
k_pipe(const float *__restrict__ x, const float *__restrict__ Wih0,
       const float *__restrict__ Whh0, const float *__restrict__ bih0,
       const float *__restrict__ bhh0, const float *__restrict__ Wih1,
       const float *__restrict__ Whh1, const float *__restrict__ bih1,
       const float *__restrict__ bhh1) {
    extern __shared__ char smem[];
    if (blockIdx.x < NPAIR)
        producer(x, Wih0, Whh0, bih0, bhh0, Wih1, bih1, bhh1, smem);
    else
        consumer(Whh1, Wih1, bih1, bhh1, smem);
}

extern "C" __global__ void k_reset() {
    if (threadIdx.x < NPAIR) g_flag[threadIdx.x] = 0u;
}

// ======== k_cls v2: 64 blocks x 256 threads, 8 rows/block, k-major SMEM weights ========
// Warp g handles batch row rb+g. Conflict-free inner loops: z1 LDS.128 16B-index = k*32+lane;
// h/z operand is warp-broadcast. After cooperative loads, all work is warp-local.
extern "C" __global__ void __launch_bounds__(256)
k_cls(const float *__restrict__ W1, const float *__restrict__ b1,
      const float *__restrict__ W2, const float *__restrict__ b2,
      const float *__restrict__ W3, const float *__restrict__ b3,
      float *__restrict__ out) {
    extern __shared__ float cs[];
    float *W1t = cs;                 // [k=128][o=128] 65536 B
    float *W2t = W1t + 128 * 128;    // [k=128][o=64]  32768 B
    float *hs = W2t + 128 * 64;      // [8][128]
    float *z1s = hs + 8 * 128;       // [8][128]
    float *z2s = z1s + 8 * 128;      // [8][64]
    float *W3s = z2s + 8 * 64;       // [6*64]
    const int tid = threadIdx.x;
    const int g = tid >> 5, lane = tid & 31;
    const int rb = blockIdx.x * 8;

    // transpose-load W1 -> W1t[k][o] (STS banks = o%32, conflict-free)
    for (int i = tid; i < 128 * 32; i += 256) {
        int k4 = i >> 7, o = i & 127;
        float4 v = *(const float4 *)(W1 + (size_t)o * 128 + k4 * 4);
        W1t[(k4 * 4 + 0) * 128 + o] = v.x;
        W1t[(k4 * 4 + 1) * 128 + o] = v.y;
        W1t[(k4 * 4 + 2) * 128 + o] = v.z;
        W1t[(k4 * 4 + 3) * 128 + o] = v.w;
    }
    for (int i = tid; i < 64 * 32; i += 256) {
        int k4 = i >> 6, o = i & 63;
        float4 v = *(const float4 *)(W2 + (size_t)o * 128 + k4 * 4);
        W2t[(k4 * 4 + 0) * 64 + o] = v.x;
        W2t[(k4 * 4 + 1) * 64 + o] = v.y;
        W2t[(k4 * 4 + 2) * 64 + o] = v.z;
        W2t[(k4 * 4 + 3) * 64 + o] = v.w;
    }
    for (int i = tid; i < 6 * 64; i += 256) W3s[i] = W3[i];
    for (int i = tid; i < 8 * 128 / 4; i += 256)
        *(float4 *)(hs + i * 4) = *(const float4 *)(g_h1f + (size_t)rb * 128 + i * 4);
    __syncthreads();

    // z1 = relu(W1 @ h + b1): lane owns outputs 4*lane..4*lane+3 of row g
    {
        const int o0 = 4 * lane;
        float acc0 = b1[o0], acc1 = b1[o0 + 1], acc2 = b1[o0 + 2], acc3 = b1[o0 + 3];
        const float *hr = hs + g * 128;
#pragma unroll 8
        for (int k = 0; k < 128; ++k) {
            const float hv = hr[k];                      // warp broadcast
            float4 wv = *(const float4 *)(W1t + k * 128 + o0);  // conflict-free
            acc0 = fmaf(wv.x, hv, acc0);
            acc1 = fmaf(wv.y, hv, acc1);
            acc2 = fmaf(wv.z, hv, acc2);
            acc3 = fmaf(wv.w, hv, acc3);
        }
        float *zr = z1s + g * 128;
        zr[o0] = fmaxf(acc0, 0.f);
        zr[o0 + 1] = fmaxf(acc1, 0.f);
        zr[o0 + 2] = fmaxf(acc2, 0.f);
        zr[o0 + 3] = fmaxf(acc3, 0.f);
    }
    __syncwarp();
    // z2 = relu(W2 @ z1 + b2): lane owns outputs 2*lane, 2*lane+1
    {
        const int o0 = 2 * lane;
        float acc0 = b2[o0], acc1 = b2[o0 + 1];
        const float *zr = z1s + g * 128;
#pragma unroll 8
        for (int k = 0; k < 128; ++k) {
            const float zv = zr[k];                      // warp broadcast
            float2 wv = *(const float2 *)(W2t + k * 64 + o0);
            acc0 = fmaf(wv.x, zv, acc0);
            acc1 = fmaf(wv.y, zv, acc1);
        }
        z2s[g * 64 + o0] = fmaxf(acc0, 0.f);
        z2s[g * 64 + o0 + 1] = fmaxf(acc1, 0.f);
    }
    __syncwarp();
    // z3 (6 logits) + double softmax
    if (lane < 6) {
        float s = b3[lane];
        const float *wr = W3s + lane * 64;
        const float *zr = z2s + g * 64;
#pragma unroll 8
        for (int k = 0; k < 64; ++k) s = fmaf(wr[k], zr[k], s);
        z1s[g * 128 + lane] = s;  // reuse z1s as logit scratch
    }
    __syncwarp();
    if (lane == 0) {
        float v[6];
#pragma unroll
        for (int i = 0; i < 6; ++i) v[i] = z1s[g * 128 + i];
#pragma unroll
        for (int p = 0; p < 2; ++p) {
            float m = v[0];
            for (int i = 1; i < 6; ++i) m = fmaxf(m, v[i]);
            float s = 0.f;
            for (int i = 0; i < 6; ++i) { v[i] = expf(v[i] - m); s += v[i]; }
            float inv = 1.f / s;
            for (int i = 0; i < 6; ++i) v[i] *= inv;
        }
        for (int i = 0; i < 6; ++i) out[(rb + g) * 6 + i] = v[i];
    }
}

extern "C" void kernel_launch(void *const *d_in, const int *in_sizes, int n_in,
                              void *d_out, int out_size) {
    const float *x = (const float *)d_in[0];
    const float *Wih0 = (const float *)d_in[1];
    const float *Whh0 = (const float *)d_in[2];
    const float *bih0 = (const float *)d_in[3];
    const float *bhh0 = (const float *)d_in[4];
    const float *Wih1 = (const float *)d_in[5];
    const float *Whh1 = (const float *)d_in[6];
    const float *bih1 = (const float *)d_in[7];
    const float *bhh1 = (const float *)d_in[8];
    const float *W1 = (const float *)d_in[9];
    const float *b1 = (const float *)d_in[10];
    const float *W2 = (const float *)d_in[11];
    const float *b2 = (const float *)d_in[12];
    const float *W3 = (const float *)d_in[13];
    const float *b3 = (const float *)d_in[14];
    float *out = (float *)d_out;

    const int SMEMP = 17152 + 69632;  // 86784 (k_pipe)
    const int SMEMC = (128 * 128 + 128 * 64 + 8 * 128 + 8 * 128 + 8 * 64 + 6 * 64) * 4;  // 110592
    cudaFuncSetAttribute(k_pipe, cudaFuncAttributeMaxDynamicSharedMemorySize, SMEMP);
    cudaFuncSetAttribute(k_cls, cudaFuncAttributeMaxDynamicSharedMemorySize, SMEMC);

    k_reset<<<1, 64>>>();
    k_pipe<<<2 * NPAIR, 256, SMEMP>>>(x, Wih0, Whh0, bih0, bhh0, Wih1, Whh1, bih1, bhh1);
    k_cls<<<BB / 8, 256, SMEMC>>>(W1, b1, W2, b2, W3, b3, out);
}

// round 16
// speedup vs baseline: 1.1034x; 1.0119x over previous
#include <cuda_runtime.h>
#include <cuda_bf16.h>
#include <math.h>

#define TT 2048
#define BB 512
#define HH 128
#define ROWS 8
#define NPAIR (BB / ROWS)   // 64 producer/consumer pairs
#define PADH 136            // h row stride (bf16)
#define XPI 264             // xg_if row stride (bf16)
#define PADW 136            // Wih1-half smem row stride (bf16)
#define CHUNK 64            // steady-state publish granularity (steps)

typedef unsigned int u32;

// scratch (static device globals: allowed; no cudaMalloc anywhere; zero-initialized at load)
static __device__ __nv_bfloat16 g_xgif[(size_t)BB * TT * 256];  // gates i,f of layer-1 input (+bias)
static __device__ __nv_bfloat16 g_h0[(size_t)BB * TT * HH];     // layer-0 hidden states
static __device__ float g_h1f[BB * HH];                         // final hidden of layer 1
static __device__ u32 g_flag[NPAIR];                            // producer progress flags

__device__ __forceinline__ float tanha(float x) {
    asm("tanh.approx.f32 %0, %0;" : "+f"(x));
    return x;
}
__device__ __forceinline__ float sigm(float x) { return fmaf(tanha(0.5f * x), 0.5f, 0.5f); }

__device__ __forceinline__ u32 pbf2(float a, float b) {
    __nv_bfloat162 t = __floats2bfloat162_rn(a, b);
    return *(u32 *)&t;
}

__device__ __forceinline__ void mma16816(float *c, const u32 *a, const u32 *b) {
    asm volatile(
        "mma.sync.aligned.m16n8k16.row.col.f32.bf16.bf16.f32 "
        "{%0,%1,%2,%3}, {%4,%5,%6,%7}, {%8,%9}, {%0,%1,%2,%3};"
        : "+f"(c[0]), "+f"(c[1]), "+f"(c[2]), "+f"(c[3])
        : "r"(a[0]), "r"(a[1]), "r"(a[2]), "r"(a[3]), "r"(b[0]), "r"(b[1]));
}

__device__ __forceinline__ void ldmx4(u32 &r0, u32 &r1, u32 &r2, u32 &r3, u32 addr) {
    asm volatile("ldmatrix.sync.aligned.m8n8.x4.shared.b16 {%0,%1,%2,%3}, [%4];"
                 : "=r"(r0), "=r"(r1), "=r"(r2), "=r"(r3) : "r"(addr));
}

__device__ __forceinline__ u32 smem_u32(const void *p) {
    u32 a;
    asm("{ .reg .u64 t; cvta.to.shared.u64 t, %1; cvt.u32.u64 %0, t; }" : "=r"(a) : "l"(p));
    return a;
}

__device__ __forceinline__ u32 ld_acq(const u32 *p) {
    u32 v;
    asm volatile("ld.global.acquire.gpu.u32 %0, [%1];" : "=r"(v) : "l"(p) : "memory");
    return v;
}
__device__ __forceinline__ void st_rel(u32 *p, u32 v) {
    asm volatile("st.global.release.gpu.u32 [%0], %1;" :: "l"(p), "r"(v) : "memory");
}

// publish condition: every CHUNK steps in steady state, every 8 steps over the final CHUNK
__device__ __forceinline__ bool do_publish(int t) {
    return ((t & (CHUNK - 1)) == 0) || (t > TT - CHUNK && (t & 7) == 0);
}

// ============ producer: layer-0 LSTM (fold in fp32) + gemm (gates i,f). 256 threads ============
__device__ __forceinline__ void producer(
    const float *__restrict__ x, const float *__restrict__ Wih0,
    const float *__restrict__ Whh0, const float *__restrict__ bih0,
    const float *__restrict__ bhh0, const float *__restrict__ Wih1,
    const float *__restrict__ bih1, const float *__restrict__ bhh1, char *smem) {
    __nv_bfloat16 *W1s = (__nv_bfloat16 *)smem;                    // [256][PADW] 69632 B (Wih1 rows 0..255)
    __nv_bfloat16 *hbuf = (__nv_bfloat16 *)(smem + 69632);         // [2][8][PADH] 4352 B
    __nv_bfloat16 *stage = (__nv_bfloat16 *)(smem + 73984);        // [2][8][XPI] 8448 B
    float2 *fslot = (float2 *)(smem + 82432);                      // [2][8] 128 B
    const int tid = threadIdx.x;
    const int w = tid >> 5, lane = tid & 31, gid = lane >> 2, tig = lane & 3;
    const int rb = blockIdx.x * ROWS;
    const int u0 = w * 16 + gid, u1 = u0 + 8;
    const int r0 = 2 * tig, r1 = r0 + 1;

    u32 a[4][8][4];
#pragma unroll
    for (int g = 0; g < 4; ++g) {
        const int gr0 = g * 128 + u0, gr1 = g * 128 + u1;
#pragma unroll
        for (int kt = 0; kt < 8; ++kt) {
            const int k = kt * 16 + 2 * tig;
            a[g][kt][0] = pbf2(Whh0[(size_t)gr0 * HH + k], Whh0[(size_t)gr0 * HH + k + 1]);
            a[g][kt][1] = pbf2(Whh0[(size_t)gr1 * HH + k], Whh0[(size_t)gr1 * HH + k + 1]);
            a[g][kt][2] = pbf2(Whh0[(size_t)gr0 * HH + k + 8], Whh0[(size_t)gr0 * HH + k + 9]);
            a[g][kt][3] = pbf2(Whh0[(size_t)gr1 * HH + k + 8], Whh0[(size_t)gr1 * HH + k + 9]);
        }
    }
    float wiA0[4], wiA1[4], wiB0[4], wiB1[4], bA[4], bB[4];
#pragma unroll
    for (int g = 0; g < 4; ++g) {
        const int ra = g * 128 + u0, rbx = g * 128 + u1;
        wiA0[g] = Wih0[ra * 2]; wiA1[g] = Wih0[ra * 2 + 1]; bA[g] = bih0[ra] + bhh0[ra];
        wiB0[g] = Wih0[rbx * 2]; wiB1[g] = Wih0[rbx * 2 + 1]; bB[g] = bih0[rbx] + bhh0[rbx];
    }
    float bxa[2], bxb[2];
#pragma unroll
    for (int q = 0; q < 2; ++q) {
        bxa[q] = bih1[q * 128 + u0] + bhh1[q * 128 + u0];
        bxb[q] = bih1[q * 128 + u1] + bhh1[q * 128 + u1];
    }
    for (int i = tid; i < 256 * 32; i += 256) {
        int row = i >> 5, kc = i & 31;
        float4 v = *(const float4 *)(Wih1 + (size_t)row * HH + kc * 4);
        *(__nv_bfloat162 *)&W1s[row * PADW + kc * 4] = __floats2bfloat162_rn(v.x, v.y);
        *(__nv_bfloat162 *)&W1s[row * PADW + kc * 4 + 2] = __floats2bfloat162_rn(v.z, v.w);
    }
    const u32 w1b = smem_u32(W1s);
    u32 ldm[2];
#pragma unroll
    for (int q = 0; q < 2; ++q) {
        const int row_l = q * 128 + w * 16 + (lane & 15);
        ldm[q] = w1b + (u32)((row_l * PADW + ((lane & 16) ? 8 : 0)) * 2);
    }
    for (int i = tid; i < 2 * ROWS * PADH / 2; i += 256) ((u32 *)hbuf)[i] = 0u;
    if (tid < ROWS) {
        const float *xp = x + ((size_t)(rb + tid) * TT) * 6;
        fslot[tid] = make_float2(sqrtf(xp[0] * xp[0] + xp[1] * xp[1] + xp[2] * xp[2]),
                                 sqrtf(xp[3] * xp[3] + xp[4] * xp[4] + xp[5] * xp[5]));
    }
    float cst[4] = {0.f, 0.f, 0.f, 0.f};
    u32 *myflag = &g_flag[blockIdx.x];
    __syncthreads();

#pragma unroll 1
    for (int t = 0; t <= TT; ++t) {
        const __nv_bfloat16 *hb = hbuf + (t & 1) * ROWS * PADH;          // h(t-1)
        __nv_bfloat16 *hn = hbuf + ((t + 1) & 1) * ROWS * PADH;          // h(t)
        u32 b[8][2];
#pragma unroll
        for (int kt = 0; kt < 8; ++kt) {
            const int base = gid * PADH + kt * 16 + 2 * tig;
            b[kt][0] = *(const u32 *)&hb[base];
            b[kt][1] = *(const u32 *)&hb[base + 8];
        }
        float pfx = 0.f, pfy = 0.f;
        const bool pfv = (tid < ROWS) && (t + 1 < TT);
        if (pfv) {
            const float *xp = x + ((size_t)(rb + tid) * TT + (t + 1)) * 6;
            pfx = sqrtf(xp[0] * xp[0] + xp[1] * xp[1] + xp[2] * xp[2]);
            pfy = sqrtf(xp[3] * xp[3] + xp[4] * xp[4] + xp[5] * xp[5]);
        }
        if (t < TT) {
            float acc[4][4];
#pragma unroll
            for (int g = 0; g < 4; ++g) { acc[g][0] = acc[g][1] = acc[g][2] = acc[g][3] = 0.f; }
#pragma unroll
            for (int kt = 0; kt < 8; ++kt)
#pragma unroll
                for (int g = 0; g < 4; ++g) mma16816(acc[g], a[g][kt], b[kt]);
            const float2 fa = fslot[(t & 1) * 8 + r0];
            const float2 fb = fslot[(t & 1) * 8 + r1];
#pragma unroll
            for (int g = 0; g < 4; ++g) {
                acc[g][0] += fmaf(wiA0[g], fa.x, fmaf(wiA1[g], fa.y, bA[g]));
                acc[g][1] += fmaf(wiA0[g], fb.x, fmaf(wiA1[g], fb.y, bA[g]));
                acc[g][2] += fmaf(wiB0[g], fa.x, fmaf(wiB1[g], fa.y, bB[g]));
                acc[g][3] += fmaf(wiB0[g], fb.x, fmaf(wiB1[g], fb.y, bB[g]));
            }
            float h[4];
#pragma unroll
            for (int s = 0; s < 4; ++s) {
                cst[s] = sigm(acc[1][s]) * cst[s] + sigm(acc[0][s]) * tanha(acc[2][s]);
                h[s] = sigm(acc[3][s]) * tanha(cst[s]);
            }
            hn[r0 * PADH + u0] = __float2bfloat16(h[0]);
            hn[r1 * PADH + u0] = __float2bfloat16(h[1]);
            hn[r0 * PADH + u1] = __float2bfloat16(h[2]);
            hn[r1 * PADH + u1] = __float2bfloat16(h[3]);
            if (pfv) fslot[((t + 1) & 1) * 8 + tid] = make_float2(pfx, pfy);
        }
        if (t > 0) {
            float xa[2][4];
            xa[0][0] = xa[0][1] = xa[0][2] = xa[0][3] = 0.f;
            xa[1][0] = xa[1][1] = xa[1][2] = xa[1][3] = 0.f;
#pragma unroll
            for (int kt = 0; kt < 8; ++kt) {
                u32 aw[4];
                ldmx4(aw[0], aw[1], aw[2], aw[3], ldm[0] + kt * 32);
                mma16816(xa[0], aw, b[kt]);
                ldmx4(aw[0], aw[1], aw[2], aw[3], ldm[1] + kt * 32);
                mma16816(xa[1], aw, b[kt]);
            }
            __nv_bfloat16 *stg = stage + (t & 1) * ROWS * XPI;
#pragma unroll
            for (int q = 0; q < 2; ++q) {
                stg[r0 * XPI + q * 128 + u0] = __float2bfloat16(xa[q][0] + bxa[q]);
                stg[r1 * XPI + q * 128 + u0] = __float2bfloat16(xa[q][1] + bxa[q]);
                stg[r0 * XPI + q * 128 + u1] = __float2bfloat16(xa[q][2] + bxb[q]);
                stg[r1 * XPI + q * 128 + u1] = __float2bfloat16(xa[q][3] + bxb[q]);
            }
        }
        __syncthreads();
        if (t < TT && tid < 128) {
            const int row = tid >> 4, q = tid & 15;
            uint4 v = *(const uint4 *)&hn[row * PADH + q * 8];
            *(uint4 *)(g_h0 + ((size_t)(rb + row) * TT + t) * HH + q * 8) = v;
        }
        if (t > 0) {
            const __nv_bfloat16 *stg = stage + (t & 1) * ROWS * XPI;
            const int row = tid >> 5, seg = tid & 31;
            uint4 v = *(const uint4 *)&stg[row * XPI + seg * 8];
            *(uint4 *)(g_xgif + ((size_t)(rb + row) * TT + (t - 1)) * 256 + seg * 8) = v;
            if (do_publish(t)) {
                __threadfence();
                __syncthreads();
                if (tid == 0) st_rel(myflag, (u32)t);
            }
        }
    }
}

// ===== consumer: layer-1 LSTM + gemm (gates g,o) from h0. 256 threads =====
__device__ __forceinline__ void consumer(
    const float *__restrict__ Whh1, const float *__restrict__ Wih1,
    const float *__restrict__ bih1, const float *__restrict__ bhh1, char *smem) {
    __nv_bfloat16 *hbuf = (__nv_bfloat16 *)smem;                   // [2][8][PADH] 4352 B
    __nv_bfloat16 *h0buf = (__nv_bfloat16 *)(smem + 4352);         // [2][8][PADH] 4352 B
    __nv_bfloat16 *xifbuf = (__nv_bfloat16 *)(smem + 8704);        // [2][8][XPI] 8448 B
    __nv_bfloat16 *W1s = (__nv_bfloat16 *)(smem + 17152);          // [256][PADW] 69632 B (rows 256..511)
    const int tid = threadIdx.x;
    const int w = tid >> 5, lane = tid & 31, gid = lane >> 2, tig = lane & 3;
    const int p = blockIdx.x - NPAIR;
    const int rb = p * ROWS;
    const int u0 = w * 16 + gid, u1 = u0 + 8;
    const int r0 = 2 * tig, r1 = r0 + 1;
    const u32 *myflag = &g_flag[p];

    u32 a[4][8][4];
#pragma unroll
    for (int g = 0; g < 4; ++g) {
        const int gr0 = g * 128 + u0, gr1 = g * 128 + u1;
#pragma unroll
        for (int kt = 0; kt < 8; ++kt) {
            const int k = kt * 16 + 2 * tig;
            a[g][kt][0] = pbf2(Whh1[(size_t)gr0 * HH + k], Whh1[(size_t)gr0 * HH + k + 1]);
            a[g][kt][1] = pbf2(Whh1[(size_t)gr1 * HH + k], Whh1[(size_t)gr1 * HH + k + 1]);
            a[g][kt][2] = pbf2(Whh1[(size_t)gr0 * HH + k + 8], Whh1[(size_t)gr0 * HH + k + 9]);
            a[g][kt][3] = pbf2(Whh1[(size_t)gr1 * HH + k + 8], Whh1[(size_t)gr1 * HH + k + 9]);
        }
    }
    const float bg0 = bih1[256 + u0] + bhh1[256 + u0];
    const float bg1 = bih1[256 + u1] + bhh1[256 + u1];
    const float bo0 = bih1[384 + u0] + bhh1[384 + u0];
    const float bo1 = bih1[384 + u1] + bhh1[384 + u1];
    for (int i = tid; i < 256 * 32; i += 256) {
        int row = i >> 5, kc = i & 31;
        float4 v = *(const float4 *)(Wih1 + (size_t)(256 + row) * HH + kc * 4);
        *(__nv_bfloat162 *)&W1s[row * PADW + kc * 4] = __floats2bfloat162_rn(v.x, v.y);
        *(__nv_bfloat162 *)&W1s[row * PADW + kc * 4 + 2] = __floats2bfloat162_rn(v.z, v.w);
    }
    const u32 w1b = smem_u32(W1s);
    u32 ldm[2];
#pragma unroll
    for (int q = 0; q < 2; ++q) {
        const int row_l = q * 128 + w * 16 + (lane & 15);
        ldm[q] = w1b + (u32)((row_l * PADW + ((lane & 16) ? 8 : 0)) * 2);
    }
    for (int i = tid; i < 2 * ROWS * PADH / 2; i += 256) ((u32 *)hbuf)[i] = 0u;
    const int xrow = tid >> 5, xseg = tid & 31;
    const int hrow = tid >> 4, hseg = tid & 15;
    u32 seen = ld_acq(myflag);
    while (seen < 1u) { __nanosleep(256); seen = ld_acq(myflag); }
    {
        uint4 v = *(const uint4 *)(g_xgif + ((size_t)(rb + xrow) * TT) * 256 + xseg * 8);
        *(uint4 *)&xifbuf[xrow * XPI + xseg * 8] = v;
        if (tid < 128) {
            uint4 hv = *(const uint4 *)(g_h0 + ((size_t)(rb + hrow) * TT) * HH + hseg * 8);
            *(uint4 *)&h0buf[hrow * PADH + hseg * 8] = hv;
        }
    }
    float cst[4] = {0.f, 0.f, 0.f, 0.f};
    __syncthreads();

#pragma unroll 1
    for (int t = 0; t < TT; ++t) {
        const int hasn = (t + 1 < TT);
        uint4 pfx, pfh;
        if (hasn) {
            const u32 need = (u32)(t + 2);
            if (seen < need) {
                seen = ld_acq(myflag);
                while (seen < need) { __nanosleep(128); seen = ld_acq(myflag); }
            }
            pfx = *(const uint4 *)(g_xgif + ((size_t)(rb + xrow) * TT + (t + 1)) * 256 + xseg * 8);
            if (tid < 128)
                pfh = *(const uint4 *)(g_h0 + ((size_t)(rb + hrow) * TT + (t + 1)) * HH + hseg * 8);
        }
        const __nv_bfloat16 *xb = xifbuf + (t & 1) * ROWS * XPI;
        const __nv_bfloat16 *hb = hbuf + (t & 1) * ROWS * PADH;
        const __nv_bfloat16 *h0b = h0buf + (t & 1) * ROWS * PADH;
        __nv_bfloat16 *hn = hbuf + ((t + 1) & 1) * ROWS * PADH;
        u32 b[8][2], b0[8][2];
#pragma unroll
        for (int kt = 0; kt < 8; ++kt) {
            const int base = gid * PADH + kt * 16 + 2 * tig;
            b[kt][0] = *(const u32 *)&hb[base];
            b[kt][1] = *(const u32 *)&hb[base + 8];
            b0[kt][0] = *(const u32 *)&h0b[base];
            b0[kt][1] = *(const u32 *)&h0b[base + 8];
        }
        float acc[4][4];
#pragma unroll
        for (int g = 0; g < 4; ++g) { acc[g][0] = acc[g][1] = acc[g][2] = acc[g][3] = 0.f; }
#pragma unroll
        for (int kt = 0; kt < 8; ++kt)
#pragma unroll
            for (int g = 0; g < 4; ++g) mma16816(acc[g], a[g][kt], b[kt]);
        float xa[2][4];
        xa[0][0] = xa[0][1] = xa[0][2] = xa[0][3] = 0.f;
        xa[1][0] = xa[1][1] = xa[1][2] = xa[1][3] = 0.f;
#pragma unroll
        for (int kt = 0; kt < 8; ++kt) {
            u32 aw[4];
            ldmx4(aw[0], aw[1], aw[2], aw[3], ldm[0] + kt * 32);
            mma16816(xa[0], aw, b0[kt]);
            ldmx4(aw[0], aw[1], aw[2], aw[3], ldm[1] + kt * 32);
            mma16816(xa[1], aw, b0[kt]);
        }
        const float gi0 = acc[0][0] + __bfloat162float(xb[r0 * XPI + u0]);
        const float gi1 = acc[0][1] + __bfloat162float(xb[r1 * XPI + u0]);
        const float gi2 = acc[0][2] + __bfloat162float(xb[r0 * XPI + u1]);
        const float gi3 = acc[0][3] + __bfloat162float(xb[r1 * XPI + u1]);
        const float gf0 = acc[1][0] + __bfloat162float(xb[r0 * XPI + 128 + u0]);
        const float gf1 = acc[1][1] + __bfloat162float(xb[r1 * XPI + 128 + u0]);
        const float gf2 = acc[1][2] + __bfloat162float(xb[r0 * XPI + 128 + u1]);
        const float gf3 = acc[1][3] + __bfloat162float(xb[r1 * XPI + 128 + u1]);
        const float gg0 = acc[2][0] + xa[0][0] + bg0;
        const float gg1 = acc[2][1] + xa[0][1] + bg0;
        const float gg2 = acc[2][2] + xa[0][2] + bg1;
        const float gg3 = acc[2][3] + xa[0][3] + bg1;
        const float go0 = acc[3][0] + xa[1][0] + bo0;
        const float go1 = acc[3][1] + xa[1][1] + bo0;
        const float go2 = acc[3][2] + xa[1][2] + bo1;
        const float go3 = acc[3][3] + xa[1][3] + bo1;
        float h[4];
        cst[0] = sigm(gf0) * cst[0] + sigm(gi0) * tanha(gg0);
        h[0] = sigm(go0) * tanha(cst[0]);
        cst[1] = sigm(gf1) * cst[1] + sigm(gi1) * tanha(gg1);
        h[1] = sigm(go1) * tanha(cst[1]);
        cst[2] = sigm(gf2) * cst[2] + sigm(gi2) * tanha(gg2);
        h[2] = sigm(go2) * tanha(cst[2]);
        cst[3] = sigm(gf3) * cst[3] + sigm(gi3) * tanha(gg3);
        h[3] = sigm(go3) * tanha(cst[3]);
        hn[r0 * PADH + u0] = __float2bfloat16(h[0]);
        hn[r1 * PADH + u0] = __float2bfloat16(h[1]);
        hn[r0 * PADH + u1] = __float2bfloat16(h[2]);
        hn[r1 * PADH + u1] = __float2bfloat16(h[3]);
        if (hasn) {
            __nv_bfloat16 *xn = xifbuf + ((t + 1) & 1) * ROWS * XPI;
            *(uint4 *)&xn[xrow * XPI + xseg * 8] = pfx;
            if (tid < 128) {
                __nv_bfloat16 *h0n = h0buf + ((t + 1) & 1) * ROWS * PADH;
                *(uint4 *)&h0n[hrow * PADH + hseg * 8] = pfh;
            }
        } else {
            g_h1f[(rb + r0) * HH + u0] = h[0];
            g_h1f[(rb + r1) * HH + u0] = h[1];
            g_h1f[(rb + r0) * HH + u1] = h[2];
            g_h1f[(rb + r1) * HH + u1] = h[3];
        }
        __syncthreads();
    }
}

extern "C" __global__ void __launch_bounds__(256, 1)
k_pipe(const float *__restrict__ x, const float *__restrict__ Wih0,
       const float *__restrict__ Whh0, const float *__restrict__ bih0,
       const float *__restrict__ bhh0, const float *__restrict__ Wih1,
       const float *__restrict__ Whh1, const float *__restrict__ bih1,
       const float *__restrict__ bhh1) {
    extern __shared__ char smem[];
    if (blockIdx.x < NPAIR)
        producer(x, Wih0, Whh0, bih0, bhh0, Wih1, bih1, bhh1, smem);
    else
        consumer(Whh1, Wih1, bih1, bhh1, smem);
}

// ======== k_cls v2 + flag reset (replaces k_reset; runs strictly after k_pipe) ========
extern "C" __global__ void __launch_bounds__(256)
k_cls(const float *__restrict__ W1, const float *__restrict__ b1,
      const float *__restrict__ W2, const float *__restrict__ b2,
      const float *__restrict__ W3, const float *__restrict__ b3,
      float *__restrict__ out) {
    extern __shared__ float cs[];
    float *W1t = cs;                 // [k=128][o=128]
    float *W2t = W1t + 128 * 128;    // [k=128][o=64]
    float *hs = W2t + 128 * 64;      // [8][128]
    float *z1s = hs + 8 * 128;       // [8][128]
    float *z2s = z1s + 8 * 128;      // [8][64]
    float *W3s = z2s + 8 * 64;       // [6*64]
    const int tid = threadIdx.x;
    const int g = tid >> 5, lane = tid & 31;
    const int rb = blockIdx.x * 8;

    if (tid == 0) g_flag[blockIdx.x] = 0u;  // reset for next graph replay (grid = NPAIR blocks)

    for (int i = tid; i < 128 * 32; i += 256) {
        int k4 = i >> 7, o = i & 127;
        float4 v = *(const float4 *)(W1 + (size_t)o * 128 + k4 * 4);
        W1t[(k4 * 4 + 0) * 128 + o] = v.x;
        W1t[(k4 * 4 + 1) * 128 + o] = v.y;
        W1t[(k4 * 4 + 2) * 128 + o] = v.z;
        W1t[(k4 * 4 + 3) * 128 + o] = v.w;
    }
    for (int i = tid; i < 64 * 32; i += 256) {
        int k4 = i >> 6, o = i & 63;
        float4 v = *(const float4 *)(W2 + (size_t)o * 128 + k4 * 4);
        W2t[(k4 * 4 + 0) * 64 + o] = v.x;
        W2t[(k4 * 4 + 1) * 64 + o] = v.y;
        W2t[(k4 * 4 + 2) * 64 + o] = v.z;
        W2t[(k4 * 4 + 3) * 64 + o] = v.w;
    }
    for (int i = tid; i < 6 * 64; i += 256) W3s[i] = W3[i];
    for (int i = tid; i < 8 * 128 / 4; i += 256)
        *(float4 *)(hs + i * 4) = *(const float4 *)(g_h1f + (size_t)rb * 128 + i * 4);
    __syncthreads();

    {
        const int o0 = 4 * lane;
        float acc0 = b1[o0], acc1 = b1[o0 + 1], acc2 = b1[o0 + 2], acc3 = b1[o0 + 3];
        const float *hr = hs + g * 128;
#pragma unroll 8
        for (int k = 0; k < 128; ++k) {
            const float hv = hr[k];
            float4 wv = *(const float4 *)(W1t + k * 128 + o0);
            acc0 = fmaf(wv.x, hv, acc0);
            acc1 = fmaf(wv.y, hv, acc1);
            acc2 = fmaf(wv.z, hv, acc2);
            acc3 = fmaf(wv.w, hv, acc3);
        }
        float *zr = z1s + g * 128;
        zr[o0] = fmaxf(acc0, 0.f);
        zr[o0 + 1] = fmaxf(acc1, 0.f);
        zr[o0 + 2] = fmaxf(acc2, 0.f);
        zr[o0 + 3] = fmaxf(acc3, 0.f);
    }
    __syncwarp();
    {
        const int o0 = 2 * lane;
        float acc0 = b2[o0], acc1 = b2[o0 + 1];
        const float *zr = z1s + g * 128;
#pragma unroll 8
        for (int k = 0; k < 128; ++k) {
            const float zv = zr[k];
            float2 wv = *(const float2 *)(W2t + k * 64 + o0);
            acc0 = fmaf(wv.x, zv, acc0);
            acc1 = fmaf(wv.y, zv, acc1);
        }
        z2s[g * 64 + o0] = fmaxf(acc0, 0.f);
        z2s[g * 64 + o0 + 1] = fmaxf(acc1, 0.f);
    }
    __syncwarp();
    if (lane < 6) {
        float s = b3[lane];
        const float *wr = W3s + lane * 64;
        const float *zr = z2s + g * 64;
#pragma unroll 8
        for (int k = 0; k < 64; ++k) s = fmaf(wr[k], zr[k], s);
        z1s[g * 128 + lane] = s;
    }
    __syncwarp();
    if (lane == 0) {
        float v[6];
#pragma unroll
        for (int i = 0; i < 6; ++i) v[i] = z1s[g * 128 + i];
#pragma unroll
        for (int p = 0; p < 2; ++p) {
            float m = v[0];
            for (int i = 1; i < 6; ++i) m = fmaxf(m, v[i]);
            float s = 0.f;
            for (int i = 0; i < 6; ++i) { v[i] = expf(v[i] - m); s += v[i]; }
            float inv = 1.f / s;
            for (int i = 0; i < 6; ++i) v[i] *= inv;
        }
        for (int i = 0; i < 6; ++i) out[(rb + g) * 6 + i] = v[i];
    }
}

extern "C" void kernel_launch(void *const *d_in, const int *in_sizes, int n_in,
                              void *d_out, int out_size) {
    const float *x = (const float *)d_in[0];
    const float *Wih0 = (const float *)d_in[1];
    const float *Whh0 = (const float *)d_in[2];
    const float *bih0 = (const float *)d_in[3];
    const float *bhh0 = (const float *)d_in[4];
    const float *Wih1 = (const float *)d_in[5];
    const float *Whh1 = (const float *)d_in[6];
    const float *bih1 = (const float *)d_in[7];
    const float *bhh1 = (const float *)d_in[8];
    const float *W1 = (const float *)d_in[9];
    const float *b1 = (const float *)d_in[10];
    const float *W2 = (const float *)d_in[11];
    const float *b2 = (const float *)d_in[12];
    const float *W3 = (const float *)d_in[13];
    const float *b3 = (const float *)d_in[14];
    float *out = (float *)d_out;

    const int SMEMP = 17152 + 69632;  // 86784 (k_pipe)
    const int SMEMC = (128 * 128 + 128 * 64 + 8 * 128 + 8 * 128 + 8 * 64 + 6 * 64) * 4;  // 110592
    cudaFuncSetAttribute(k_pipe, cudaFuncAttributeMaxDynamicSharedMemorySize, SMEMP);
    cudaFuncSetAttribute(k_cls, cudaFuncAttributeMaxDynamicSharedMemorySize, SMEMC);

    k_pipe<<<2 * NPAIR, 256, SMEMP>>>(x, Wih0, Whh0, bih0, bhh0, Wih1, Whh1, bih1, bhh1);
    k_cls<<<BB / 8, 256, SMEMC>>>(W1, b1, W2, b2, W3, b3, out);
}